// round 15
// baseline (speedup 1.0000x reference)
#include <cuda_runtime.h>
#include <cuda_bf16.h>
#include <cuda_pipeline.h>
#include <math.h>

// Problem dims (fixed by reference setup_inputs)
constexpr int Bc = 32;
constexpr int Tc = 4;
constexpr int Lc = 196;
constexpr int Dc = 384;
constexpr int Hc = 1536;
constexpr int Mrows = Tc * Bc * Lc;   // 25088
constexpr int NB1 = Hc / 128;         // 12 n-blocks in gemm1
constexpr int MWORDS = Hc / 64;       // 24 uint64 mask words per row

// Sparse gemm2 config: 512 threads, 2 CTAs/SM (96KB smem each, regs<=64)
constexpr int CHUNK = 32;                 // k per smem chunk
constexpr int NCHUNK = Hc / CHUNK;        // 48
constexpr int CHUNK_FLOATS = CHUNK * Dc;  // 12288 floats = 48KB
constexpr int SP_THREADS = 512;           // 16 warps
constexpr int SP_ROWS = 32;               // 2 rows per warp

// Scratch (device globals; allocation-free per harness rules)
__device__ float g_h1[(size_t)Mrows * Hc];   // pre-LN GEMM1 output  (~154 MB)
__device__ float g_h2[(size_t)Mrows * Dc];   // pre-LN GEMM2 output  (~38 MB)
__device__ float2 g_p1[(size_t)Mrows * NB1]; // (sum, sumsq) partials layer 1
__device__ float g_w2t[(size_t)Hc * Dc];     // W2 transposed [k][d] (2.4 MB)
__device__ float2 g_st2[Mrows];              // (mu, rstd) per layer-2 row
__device__ unsigned long long g_m1[(size_t)Mrows * MWORDS]; // spike bitmasks

// ---------------------------------------------------------------------------
// Packed f32x2 helpers. Each packed op = two INDEPENDENT IEEE-RN fp32 ops,
// bit-identical to the scalar __fmaf_rn / __fadd_rn pair.
// ---------------------------------------------------------------------------
union F4U { float4 f; unsigned long long u[2]; };
union A2U { unsigned long long u; float f[2]; };

__device__ __forceinline__ unsigned long long bcast2(float a) {
    unsigned long long r;
    asm("mov.b64 %0, {%1, %1};" : "=l"(r) : "f"(a));
    return r;
}
#define FMA2(ACC, A, B) \
    asm("fma.rn.f32x2 %0, %1, %2, %0;" : "+l"(ACC) : "l"(A), "l"(B))
#define ADD2(ACC, W) \
    asm("add.rn.f32x2 %0, %0, %1;" : "+l"(ACC) : "l"(W))

#define P4(a, b, c, d) (((a) + (b)) + ((c) + (d)))

// ---------------------------------------------------------------------------
// GEMM1: 128x128 tile, BK=8, 256 threads, 8x8/thread (4+4 split,
// conflict-free), double-buffered, 2 CTAs/SM. Inner loop uses packed FFMA2:
// per element the chain is STILL one fp32 RN FMA per k, ascending 0..K-1
// (packing pairs adjacent n-columns; lanes are independent). Bias separate.
// Epilogue emits per-row (sum,sumsq) partials.
// ---------------------------------------------------------------------------
__global__ __launch_bounds__(256, 2) void gemm1_kernel(
    const float* __restrict__ x, const float* __restrict__ W1,
    const float* __restrict__ b1) {
    constexpr int BK = 8;
    constexpr int LDS_ = 132;
    __shared__ float As[2][BK][LDS_];
    __shared__ float Bs[2][BK][LDS_];
    __shared__ float sp[16][132];
    __shared__ float sq[16][132];
    const int tid = threadIdx.x;
    const int lr = tid >> 1;
    const int lc = (tid & 1) * 4;

    // A row r = (t*B + b)*L + l maps into x at ((b*T + t)*L + l)*D
    const int r_ = blockIdx.y * 128 + lr;
    const int l_  = r_ % Lc;
    const int tb_ = r_ / Lc;
    const int bI_ = tb_ % Bc;
    const int tI_ = tb_ / Bc;
    const float* aptr = x + (size_t)((bI_ * Tc + tI_) * Lc + l_) * Dc + lc;
    const float* bptr = W1 + (size_t)(blockIdx.x * 128 + lr) * Dc + lc;

    const int tx = tid & 15;
    const int ty = tid >> 4;
    unsigned long long acc2[8][4];
#pragma unroll
    for (int i = 0; i < 8; i++)
#pragma unroll
        for (int j = 0; j < 4; j++) acc2[i][j] = 0ULL;  // two +0.0f

    float4 av = *(const float4*)aptr;
    float4 bv = *(const float4*)bptr;
    int buf = 0;
    As[0][lc + 0][lr] = av.x; As[0][lc + 1][lr] = av.y;
    As[0][lc + 2][lr] = av.z; As[0][lc + 3][lr] = av.w;
    Bs[0][lc + 0][lr] = bv.x; Bs[0][lc + 1][lr] = bv.y;
    Bs[0][lc + 2][lr] = bv.z; Bs[0][lc + 3][lr] = bv.w;
    __syncthreads();
    for (int k0 = BK; k0 < Dc + BK; k0 += BK) {
        const bool more = (k0 < Dc);
        if (more) {
            av = *(const float4*)(aptr + k0);
            bv = *(const float4*)(bptr + k0);
        }
#pragma unroll
        for (int k = 0; k < BK; k++) {
            F4U a0, a1, b0, b1;
            a0.f = *(const float4*)&As[buf][k][ty * 4];
            a1.f = *(const float4*)&As[buf][k][64 + ty * 4];
            b0.f = *(const float4*)&Bs[buf][k][tx * 4];
            b1.f = *(const float4*)&Bs[buf][k][64 + tx * 4];
            const float am[8] = {a0.f.x, a0.f.y, a0.f.z, a0.f.w,
                                 a1.f.x, a1.f.y, a1.f.z, a1.f.w};
            const unsigned long long bp[4] = {b0.u[0], b0.u[1], b1.u[0], b1.u[1]};
#pragma unroll
            for (int i = 0; i < 8; i++) {
                const unsigned long long ai = bcast2(am[i]);
                FMA2(acc2[i][0], ai, bp[0]);
                FMA2(acc2[i][1], ai, bp[1]);
                FMA2(acc2[i][2], ai, bp[2]);
                FMA2(acc2[i][3], ai, bp[3]);
            }
        }
        if (more) {
            buf ^= 1;
            As[buf][lc + 0][lr] = av.x; As[buf][lc + 1][lr] = av.y;
            As[buf][lc + 2][lr] = av.z; As[buf][lc + 3][lr] = av.w;
            Bs[buf][lc + 0][lr] = bv.x; Bs[buf][lc + 1][lr] = bv.y;
            Bs[buf][lc + 2][lr] = bv.z; Bs[buf][lc + 3][lr] = bv.w;
            __syncthreads();
        }
    }
    const int n_base = blockIdx.x * 128;
    const int m_base = blockIdx.y * 128;
    const float4 bb0 = *(const float4*)(b1 + n_base + tx * 4);
    const float4 bb1 = *(const float4*)(b1 + n_base + 64 + tx * 4);
#pragma unroll
    for (int i = 0; i < 8; i++) {
        float acc[8];
#pragma unroll
        for (int j = 0; j < 4; j++) {
            A2U t; t.u = acc2[i][j];
            acc[j * 2] = t.f[0]; acc[j * 2 + 1] = t.f[1];
        }
        const int ml = (i < 4) ? (ty * 4 + i) : (64 + ty * 4 + i - 4);
        float* o = g_h1 + (size_t)(m_base + ml) * Hc + n_base;
        float4 o0, o1;
        o0.x = __fadd_rn(acc[0], bb0.x); o0.y = __fadd_rn(acc[1], bb0.y);
        o0.z = __fadd_rn(acc[2], bb0.z); o0.w = __fadd_rn(acc[3], bb0.w);
        o1.x = __fadd_rn(acc[4], bb1.x); o1.y = __fadd_rn(acc[5], bb1.y);
        o1.z = __fadd_rn(acc[6], bb1.z); o1.w = __fadd_rn(acc[7], bb1.w);
        *(float4*)(o + tx * 4) = o0;
        *(float4*)(o + 64 + tx * 4) = o1;
        sp[tx][ml] = P4(o0.x, o0.y, o0.z, o0.w) + P4(o1.x, o1.y, o1.z, o1.w);
        sq[tx][ml] = P4(o0.x * o0.x, o0.y * o0.y, o0.z * o0.z, o0.w * o0.w) +
                     P4(o1.x * o1.x, o1.y * o1.y, o1.z * o1.z, o1.w * o1.w);
    }
    __syncthreads();
    if (tid < 128) {
        float a = P4(P4(sp[0][tid], sp[1][tid], sp[2][tid], sp[3][tid]),
                     P4(sp[4][tid], sp[5][tid], sp[6][tid], sp[7][tid]),
                     P4(sp[8][tid], sp[9][tid], sp[10][tid], sp[11][tid]),
                     P4(sp[12][tid], sp[13][tid], sp[14][tid], sp[15][tid]));
        float b = P4(P4(sq[0][tid], sq[1][tid], sq[2][tid], sq[3][tid]),
                     P4(sq[4][tid], sq[5][tid], sq[6][tid], sq[7][tid]),
                     P4(sq[8][tid], sq[9][tid], sq[10][tid], sq[11][tid]),
                     P4(sq[12][tid], sq[13][tid], sq[14][tid], sq[15][tid]));
        g_p1[(size_t)(m_base + tid) * NB1 + blockIdx.x] = make_float2(a, b);
    }
}

// ---------------------------------------------------------------------------
// W2 transpose: W2 [D][H] -> g_w2t [H][D].
// ---------------------------------------------------------------------------
__global__ void w2t_kernel(const float* __restrict__ W2) {
    __shared__ float tile[32][33];
    const int kb = blockIdx.x * 32, db = blockIdx.y * 32;
    const int tx = threadIdx.x, ty = threadIdx.y;
    for (int i = ty; i < 32; i += 8)
        tile[i][tx] = W2[(size_t)(db + i) * Hc + kb + tx];
    __syncthreads();
    for (int i = ty; i < 32; i += 8)
        g_w2t[(size_t)(kb + i) * Dc + db + tx] = tile[tx][i];
}

// ---------------------------------------------------------------------------
// Combine gemm1 partials -> (mu, rstd). f64 pairwise; var = E[y^2] - mu^2.
// ---------------------------------------------------------------------------
__device__ __forceinline__ float2 stats_from_p1(const float2* p) {
    double s[NB1], q[NB1];
#pragma unroll
    for (int j = 0; j < NB1; j++) { float2 v = p[j]; s[j] = v.x; q[j] = v.y; }
    const double S = (((s[0] + s[1]) + (s[2] + s[3])) +
                      ((s[4] + s[5]) + (s[6] + s[7]))) +
                     ((s[8] + s[9]) + (s[10] + s[11]));
    const double Q = (((q[0] + q[1]) + (q[2] + q[3])) +
                      ((q[4] + q[5]) + (q[6] + q[7]))) +
                     ((q[8] + q[9]) + (q[10] + q[11]));
    const double mu_d = S / (double)Hc;
    const float mu = (float)mu_d;
    const float var = (float)(Q / (double)Hc - mu_d * mu_d);
    return make_float2(mu, __fdiv_rn(1.0f, __fsqrt_rn(__fadd_rn(var, 1e-5f))));
}

// Elementwise LIF step, bit-exact op sequence (no contraction):
#define LIF_STEP(Y, G, B, V, S)                                                \
    {                                                                          \
        const float yy = __fadd_rn(                                            \
            __fmul_rn(__fmul_rn(__fsub_rn((Y), mu), rs), (G)), (B));           \
        (V) = __fadd_rn((V), __fmul_rn(__fsub_rn(yy, (V)), 0.5f));             \
        (S) = ((V) >= 1.0f) ? 1.f : 0.f;                                       \
        (V) = __fmul_rn((V), __fsub_rn(1.0f, (S)));                            \
    }

// ---------------------------------------------------------------------------
// LIF layer 1: one block per (b,l); 384 threads x float4 cover H=1536.
// Emits PACKED BITMASKS (uint64 per 64 columns), k ascending by bit.
// ---------------------------------------------------------------------------
__global__ __launch_bounds__(384) void lif1_kernel(
    const float* __restrict__ g1, const float* __restrict__ be1) {
    __shared__ float2 st[Tc];
    const int bl = blockIdx.x;
    const int bI = bl / Lc, l = bl % Lc;
    const int rbase = bI * Lc + l;
    if (threadIdx.x < Tc) {
        const int r = threadIdx.x * (Bc * Lc) + rbase;
        st[threadIdx.x] = stats_from_p1(g_p1 + (size_t)r * NB1);
    }
    const int c = threadIdx.x * 4;
    const int wp = threadIdx.x >> 5;
    const int lane = threadIdx.x & 31;
    const unsigned FULL = 0xffffffffu;
    const float4 gg = *(const float4*)(g1 + c);
    const float4 bb = *(const float4*)(be1 + c);
    float4 v = {0.f, 0.f, 0.f, 0.f};
    __syncthreads();
#pragma unroll
    for (int t = 0; t < Tc; t++) {
        const int r = t * (Bc * Lc) + rbase;
        const size_t off = (size_t)r * Hc + c;
        const float4 y = *(const float4*)(g_h1 + off);
        const float mu = st[t].x, rs = st[t].y;
        float4 sp;
        LIF_STEP(y.x, gg.x, bb.x, v.x, sp.x)
        LIF_STEP(y.y, gg.y, bb.y, v.y, sp.y)
        LIF_STEP(y.z, gg.z, bb.z, v.z, sp.z)
        LIF_STEP(y.w, gg.w, bb.w, v.w, sp.w)
        const unsigned mm = (sp.x != 0.f ? 1u : 0u) | (sp.y != 0.f ? 2u : 0u) |
                            (sp.z != 0.f ? 4u : 0u) | (sp.w != 0.f ? 8u : 0u);
        unsigned long long m = (unsigned long long)mm << ((lane & 15) * 4);
        m |= __shfl_xor_sync(FULL, m, 1);
        m |= __shfl_xor_sync(FULL, m, 2);
        m |= __shfl_xor_sync(FULL, m, 4);
        m |= __shfl_xor_sync(FULL, m, 8);
        if ((lane & 15) == 0)
            g_m1[(size_t)r * MWORDS + 2 * wp + (lane >> 4)] = m;
    }
}

// ---------------------------------------------------------------------------
// Sparse-exact GEMM2: h2[m,d] = b2[d] + sum_{k: spike(m,k)} W2T[k,d], adds in
// ascending k. Bit-identical to the dense fp32 fma chain (fma(0,..)=acc,
// fma(1,w,acc)=fadd_rn(acc,w); acc never -0). Walk adds use packed ADD2
// (lane-wise RN fp32, same arithmetic).
// 512 threads (16 warps x 2 rows = 32 rows/CTA), CHUNK=32, 2 CTAs/SM.
// ---------------------------------------------------------------------------
__global__ __launch_bounds__(SP_THREADS, 2) void spmm2_kernel(
    const float* __restrict__ b2) {
    extern __shared__ float w2s[];   // 2 * CHUNK_FLOATS (96KB)
    const int tid = threadIdx.x;
    const int warp = tid >> 5, lane = tid & 31;
    const int rbase = blockIdx.x * SP_ROWS + warp * 2;
    const int lane12 = lane * 12;
    const unsigned FULL = 0xffffffffu;

    // prologue: async copy chunk 0 (3072 float4s, 512 threads x 6)
    {
        const float4* src = (const float4*)g_w2t;
        float4* dst = (float4*)w2s;
#pragma unroll
        for (int i = 0; i < 6; i++)
            __pipeline_memcpy_async(dst + tid + i * 512, src + tid + i * 512, 16);
        __pipeline_commit();
    }

    const unsigned long long* mrow0 = g_m1 + (size_t)rbase * MWORDS;
    const unsigned long long* mrow1 = g_m1 + (size_t)(rbase + 1) * MWORDS;

    unsigned long long A[2][6];
#pragma unroll
    for (int r = 0; r < 2; r++)
#pragma unroll
        for (int j = 0; j < 6; j++) A[r][j] = 0ULL;

    for (int c = 0; c < NCHUNK; c++) {
        const int sh = (c & 1) * 32;
        unsigned u0 = (unsigned)(mrow0[c >> 1] >> sh);
        unsigned u1 = (unsigned)(mrow1[c >> 1] >> sh);
        __syncthreads();   // all warps done reading buf[(c+1)&1] (chunk c-1)
        if (c + 1 < NCHUNK) {
            const float4* src = (const float4*)(g_w2t + (size_t)(c + 1) * CHUNK_FLOATS);
            float4* dst = (float4*)(w2s + ((c + 1) & 1) * CHUNK_FLOATS);
#pragma unroll
            for (int i = 0; i < 6; i++)
                __pipeline_memcpy_async(dst + tid + i * 512, src + tid + i * 512, 16);
            __pipeline_commit();
            __pipeline_wait_prior(1);
        } else {
            __pipeline_wait_prior(0);
        }
        __syncthreads();   // chunk c resident in buf[c&1]

        const float* wbase = w2s + (c & 1) * CHUNK_FLOATS + lane12;
        while (u0 | u1) {
            if (u0) {
                const int j = __ffs(u0) - 1;
                u0 &= u0 - 1;
                F4U w0, w1, w2v;
                const float4* wr = (const float4*)(wbase + j * Dc);
                w0.f = wr[0]; w1.f = wr[1]; w2v.f = wr[2];
                ADD2(A[0][0], w0.u[0]); ADD2(A[0][1], w0.u[1]);
                ADD2(A[0][2], w1.u[0]); ADD2(A[0][3], w1.u[1]);
                ADD2(A[0][4], w2v.u[0]); ADD2(A[0][5], w2v.u[1]);
            }
            if (u1) {
                const int j = __ffs(u1) - 1;
                u1 &= u1 - 1;
                F4U w0, w1, w2v;
                const float4* wr = (const float4*)(wbase + j * Dc);
                w0.f = wr[0]; w1.f = wr[1]; w2v.f = wr[2];
                ADD2(A[1][0], w0.u[0]); ADD2(A[1][1], w0.u[1]);
                ADD2(A[1][2], w1.u[0]); ADD2(A[1][3], w1.u[1]);
                ADD2(A[1][4], w2v.u[0]); ADD2(A[1][5], w2v.u[1]);
            }
        }
    }

    // epilogue: bias, store h2, per-row stats
    const float4 bb0 = *(const float4*)(b2 + lane12);
    const float4 bb1 = *(const float4*)(b2 + lane12 + 4);
    const float4 bb2 = *(const float4*)(b2 + lane12 + 8);
#pragma unroll
    for (int rr = 0; rr < 2; rr++) {
        float acc[12];
#pragma unroll
        for (int j = 0; j < 6; j++) {
            A2U t; t.u = A[rr][j];
            acc[j * 2] = t.f[0]; acc[j * 2 + 1] = t.f[1];
        }
        float4 o0, o1, o2;
        o0.x = __fadd_rn(acc[0], bb0.x); o0.y = __fadd_rn(acc[1], bb0.y);
        o0.z = __fadd_rn(acc[2], bb0.z); o0.w = __fadd_rn(acc[3], bb0.w);
        o1.x = __fadd_rn(acc[4], bb1.x); o1.y = __fadd_rn(acc[5], bb1.y);
        o1.z = __fadd_rn(acc[6], bb1.z); o1.w = __fadd_rn(acc[7], bb1.w);
        o2.x = __fadd_rn(acc[8], bb2.x); o2.y = __fadd_rn(acc[9], bb2.y);
        o2.z = __fadd_rn(acc[10], bb2.z); o2.w = __fadd_rn(acc[11], bb2.w);
        const int row = rbase + rr;
        float* q = g_h2 + (size_t)row * Dc + lane12;
        *(float4*)q = o0; *(float4*)(q + 4) = o1; *(float4*)(q + 8) = o2;

        // f32 lane partials, f64 butterfly (same accuracy class as g_p1 path)
        const float sf = P4(o0.x, o0.y, o0.z, o0.w) +
                         P4(o1.x, o1.y, o1.z, o1.w) +
                         P4(o2.x, o2.y, o2.z, o2.w);
        const float qf = P4(o0.x * o0.x, o0.y * o0.y, o0.z * o0.z, o0.w * o0.w) +
                         P4(o1.x * o1.x, o1.y * o1.y, o1.z * o1.z, o1.w * o1.w) +
                         P4(o2.x * o2.x, o2.y * o2.y, o2.z * o2.z, o2.w * o2.w);
        double sd = (double)sf, qd = (double)qf;
#pragma unroll
        for (int o = 16; o; o >>= 1) {
            sd += __shfl_xor_sync(FULL, sd, o);
            qd += __shfl_xor_sync(FULL, qd, o);
        }
        if (lane == 0) {
            const double mu_d = sd / (double)Dc;
            const float var = (float)(qd / (double)Dc - mu_d * mu_d);
            g_st2[row] = make_float2(
                (float)mu_d,
                __fdiv_rn(1.0f, __fsqrt_rn(__fadd_rn(var, 1e-5f))));
        }
    }
}

// ---------------------------------------------------------------------------
// LIF layer 2 -> final output [B,T,L,D]. 384 threads = 4 (b,l) rows x 96
// lanes x float4 (D=384). Stats read from g_st2.
// ---------------------------------------------------------------------------
__global__ __launch_bounds__(384) void lif2_kernel(
    const float* __restrict__ g2, const float* __restrict__ be2,
    float* __restrict__ out) {
    __shared__ float2 st[4][Tc];
    if (threadIdx.x < 16) {
        const int sub_ = threadIdx.x >> 2;
        const int t_ = threadIdx.x & 3;
        const int bl_ = blockIdx.x * 4 + sub_;
        const int r = t_ * (Bc * Lc) + (bl_ / Lc) * Lc + (bl_ % Lc);
        st[sub_][t_] = g_st2[r];
    }
    const int sub = threadIdx.x / 96;        // 0..3
    const int bl = blockIdx.x * 4 + sub;
    const int bI = bl / Lc, l = bl % Lc;
    const int c = (threadIdx.x % 96) * 4;
    const float4 gg = *(const float4*)(g2 + c);
    const float4 bb = *(const float4*)(be2 + c);
    float4 v = {0.f, 0.f, 0.f, 0.f};
    const int rbase = bI * Lc + l;
    __syncthreads();
#pragma unroll
    for (int t = 0; t < Tc; t++) {
        const int r = t * (Bc * Lc) + rbase;
        const size_t off = (size_t)r * Dc + c;
        const float4 y = *(const float4*)(g_h2 + off);
        const float mu = st[sub][t].x, rs = st[sub][t].y;
        float4 sp;
        LIF_STEP(y.x, gg.x, bb.x, v.x, sp.x)
        LIF_STEP(y.y, gg.y, bb.y, v.y, sp.y)
        LIF_STEP(y.z, gg.z, bb.z, v.z, sp.z)
        LIF_STEP(y.w, gg.w, bb.w, v.w, sp.w)
        const size_t oo = (size_t)((bI * Tc + t) * Lc + l) * Dc + c;
        *(float4*)(out + oo) = sp;
    }
}

// ---------------------------------------------------------------------------
extern "C" void kernel_launch(void* const* d_in, const int* in_sizes, int n_in,
                              void* d_out, int out_size) {
    const float* x   = (const float*)d_in[0];
    const float* W1  = (const float*)d_in[1];
    const float* b1  = (const float*)d_in[2];
    const float* g1  = (const float*)d_in[3];
    const float* be1 = (const float*)d_in[4];
    const float* W2  = (const float*)d_in[5];
    const float* b2  = (const float*)d_in[6];
    const float* g2  = (const float*)d_in[7];
    const float* be2 = (const float*)d_in[8];
    float* out = (float*)d_out;

    cudaFuncSetAttribute(spmm2_kernel,
                         cudaFuncAttributeMaxDynamicSharedMemorySize,
                         2 * CHUNK_FLOATS * (int)sizeof(float));

    w2t_kernel<<<dim3(Hc / 32, Dc / 32), dim3(32, 8)>>>(W2);
    gemm1_kernel<<<dim3(Hc / 128, Mrows / 128), 256>>>(x, W1, b1);
    lif1_kernel<<<Bc * Lc, 384>>>(g1, be1);
    spmm2_kernel<<<Mrows / SP_ROWS, SP_THREADS,
                   2 * CHUNK_FLOATS * sizeof(float)>>>(b2);
    lif2_kernel<<<(Bc * Lc) / 4, 384>>>(g2, be2, out);
}

// round 16
// speedup vs baseline: 1.0528x; 1.0528x over previous
#include <cuda_runtime.h>
#include <cuda_bf16.h>
#include <cuda_pipeline.h>
#include <math.h>

// Problem dims (fixed by reference setup_inputs)
constexpr int Bc = 32;
constexpr int Tc = 4;
constexpr int Lc = 196;
constexpr int Dc = 384;
constexpr int Hc = 1536;
constexpr int Mrows = Tc * Bc * Lc;   // 25088
constexpr int NB1 = Hc / 128;         // 12 n-blocks in gemm1
constexpr int MWORDS = Hc / 64;       // 24 uint64 mask words per row

// Sparse gemm2 config: 512 threads, 2 CTAs/SM (96KB smem each, regs<=64)
constexpr int CHUNK = 32;                 // k per smem chunk
constexpr int NCHUNK = Hc / CHUNK;        // 48
constexpr int CHUNK_FLOATS = CHUNK * Dc;  // 12288 floats = 48KB
constexpr int SP_THREADS = 512;           // 16 warps
constexpr int SP_ROWS = 32;               // 2 rows per warp

// Scratch (device globals; allocation-free per harness rules)
__device__ float g_h1[(size_t)Mrows * Hc];   // pre-LN GEMM1 output  (~154 MB)
__device__ float g_h2[(size_t)Mrows * Dc];   // pre-LN GEMM2 output  (~38 MB)
__device__ float2 g_p1[(size_t)Mrows * NB1]; // (sum, sumsq) partials layer 1
__device__ float g_w2t[(size_t)Hc * Dc];     // W2 transposed [k][d] (2.4 MB)
__device__ float2 g_st2[Mrows];              // (mu, rstd) per layer-2 row
__device__ unsigned long long g_m1[(size_t)Mrows * MWORDS]; // spike bitmasks

// ---------------------------------------------------------------------------
// GEMM1 (R14 scalar, proven): 128x128 tile, BK=8, 256 threads, 8x8/thread
// (4+4 split, conflict-free), double-buffered, 2 CTAs/SM, epilogue emits
// per-row (sum,sumsq) partials.
// Bit-exact: each output is ONE fp32 FMA chain ascending k; bias separate.
// ---------------------------------------------------------------------------
#define P4(a, b, c, d) (((a) + (b)) + ((c) + (d)))

__global__ __launch_bounds__(256, 2) void gemm1_kernel(
    const float* __restrict__ x, const float* __restrict__ W1,
    const float* __restrict__ b1) {
    constexpr int BK = 8;
    constexpr int LDS_ = 132;
    __shared__ float As[2][BK][LDS_];
    __shared__ float Bs[2][BK][LDS_];
    __shared__ float sp[16][132];
    __shared__ float sq[16][132];
    const int tid = threadIdx.x;
    const int lr = tid >> 1;
    const int lc = (tid & 1) * 4;

    // A row r = (t*B + b)*L + l maps into x at ((b*T + t)*L + l)*D
    const int r_ = blockIdx.y * 128 + lr;
    const int l_  = r_ % Lc;
    const int tb_ = r_ / Lc;
    const int bI_ = tb_ % Bc;
    const int tI_ = tb_ / Bc;
    const float* aptr = x + (size_t)((bI_ * Tc + tI_) * Lc + l_) * Dc + lc;
    const float* bptr = W1 + (size_t)(blockIdx.x * 128 + lr) * Dc + lc;

    const int tx = tid & 15;
    const int ty = tid >> 4;
    float acc[8][8] = {};
    float4 av = *(const float4*)aptr;
    float4 bv = *(const float4*)bptr;
    int buf = 0;
    As[0][lc + 0][lr] = av.x; As[0][lc + 1][lr] = av.y;
    As[0][lc + 2][lr] = av.z; As[0][lc + 3][lr] = av.w;
    Bs[0][lc + 0][lr] = bv.x; Bs[0][lc + 1][lr] = bv.y;
    Bs[0][lc + 2][lr] = bv.z; Bs[0][lc + 3][lr] = bv.w;
    __syncthreads();
    for (int k0 = BK; k0 < Dc + BK; k0 += BK) {
        const bool more = (k0 < Dc);
        if (more) {
            av = *(const float4*)(aptr + k0);
            bv = *(const float4*)(bptr + k0);
        }
#pragma unroll
        for (int k = 0; k < BK; k++) {
            const float4 a0 = *(const float4*)&As[buf][k][ty * 4];
            const float4 a1 = *(const float4*)&As[buf][k][64 + ty * 4];
            const float4 b0 = *(const float4*)&Bs[buf][k][tx * 4];
            const float4 b1 = *(const float4*)&Bs[buf][k][64 + tx * 4];
            const float am[8] = {a0.x, a0.y, a0.z, a0.w, a1.x, a1.y, a1.z, a1.w};
            const float bn[8] = {b0.x, b0.y, b0.z, b0.w, b1.x, b1.y, b1.z, b1.w};
#pragma unroll
            for (int i = 0; i < 8; i++) {
#pragma unroll
                for (int j = 0; j < 8; j++)
                    acc[i][j] = __fmaf_rn(am[i], bn[j], acc[i][j]);
            }
        }
        if (more) {
            buf ^= 1;
            As[buf][lc + 0][lr] = av.x; As[buf][lc + 1][lr] = av.y;
            As[buf][lc + 2][lr] = av.z; As[buf][lc + 3][lr] = av.w;
            Bs[buf][lc + 0][lr] = bv.x; Bs[buf][lc + 1][lr] = bv.y;
            Bs[buf][lc + 2][lr] = bv.z; Bs[buf][lc + 3][lr] = bv.w;
            __syncthreads();
        }
    }
    const int n_base = blockIdx.x * 128;
    const int m_base = blockIdx.y * 128;
    const float4 bb0 = *(const float4*)(b1 + n_base + tx * 4);
    const float4 bb1 = *(const float4*)(b1 + n_base + 64 + tx * 4);
#pragma unroll
    for (int i = 0; i < 8; i++) {
        const int ml = (i < 4) ? (ty * 4 + i) : (64 + ty * 4 + i - 4);
        float* o = g_h1 + (size_t)(m_base + ml) * Hc + n_base;
        float4 o0, o1;
        o0.x = __fadd_rn(acc[i][0], bb0.x); o0.y = __fadd_rn(acc[i][1], bb0.y);
        o0.z = __fadd_rn(acc[i][2], bb0.z); o0.w = __fadd_rn(acc[i][3], bb0.w);
        o1.x = __fadd_rn(acc[i][4], bb1.x); o1.y = __fadd_rn(acc[i][5], bb1.y);
        o1.z = __fadd_rn(acc[i][6], bb1.z); o1.w = __fadd_rn(acc[i][7], bb1.w);
        *(float4*)(o + tx * 4) = o0;
        *(float4*)(o + 64 + tx * 4) = o1;
        sp[tx][ml] = P4(o0.x, o0.y, o0.z, o0.w) + P4(o1.x, o1.y, o1.z, o1.w);
        sq[tx][ml] = P4(o0.x * o0.x, o0.y * o0.y, o0.z * o0.z, o0.w * o0.w) +
                     P4(o1.x * o1.x, o1.y * o1.y, o1.z * o1.z, o1.w * o1.w);
    }
    __syncthreads();
    if (tid < 128) {
        float a = P4(P4(sp[0][tid], sp[1][tid], sp[2][tid], sp[3][tid]),
                     P4(sp[4][tid], sp[5][tid], sp[6][tid], sp[7][tid]),
                     P4(sp[8][tid], sp[9][tid], sp[10][tid], sp[11][tid]),
                     P4(sp[12][tid], sp[13][tid], sp[14][tid], sp[15][tid]));
        float b = P4(P4(sq[0][tid], sq[1][tid], sq[2][tid], sq[3][tid]),
                     P4(sq[4][tid], sq[5][tid], sq[6][tid], sq[7][tid]),
                     P4(sq[8][tid], sq[9][tid], sq[10][tid], sq[11][tid]),
                     P4(sq[12][tid], sq[13][tid], sq[14][tid], sq[15][tid]));
        g_p1[(size_t)(m_base + tid) * NB1 + blockIdx.x] = make_float2(a, b);
    }
}

// ---------------------------------------------------------------------------
// W2 transpose: W2 [D][H] -> g_w2t [H][D].
// ---------------------------------------------------------------------------
__global__ void w2t_kernel(const float* __restrict__ W2) {
    __shared__ float tile[32][33];
    const int kb = blockIdx.x * 32, db = blockIdx.y * 32;
    const int tx = threadIdx.x, ty = threadIdx.y;
    for (int i = ty; i < 32; i += 8)
        tile[i][tx] = W2[(size_t)(db + i) * Hc + kb + tx];
    __syncthreads();
    for (int i = ty; i < 32; i += 8)
        g_w2t[(size_t)(kb + i) * Dc + db + tx] = tile[tx][i];
}

// ---------------------------------------------------------------------------
// Combine gemm1 partials -> (mu, rstd). f64 pairwise; var = E[y^2] - mu^2.
// ---------------------------------------------------------------------------
__device__ __forceinline__ float2 stats_from_p1(const float2* p) {
    double s[NB1], q[NB1];
#pragma unroll
    for (int j = 0; j < NB1; j++) { float2 v = p[j]; s[j] = v.x; q[j] = v.y; }
    const double S = (((s[0] + s[1]) + (s[2] + s[3])) +
                      ((s[4] + s[5]) + (s[6] + s[7]))) +
                     ((s[8] + s[9]) + (s[10] + s[11]));
    const double Q = (((q[0] + q[1]) + (q[2] + q[3])) +
                      ((q[4] + q[5]) + (q[6] + q[7]))) +
                     ((q[8] + q[9]) + (q[10] + q[11]));
    const double mu_d = S / (double)Hc;
    const float mu = (float)mu_d;
    const float var = (float)(Q / (double)Hc - mu_d * mu_d);
    return make_float2(mu, __fdiv_rn(1.0f, __fsqrt_rn(__fadd_rn(var, 1e-5f))));
}

// Elementwise LIF step, bit-exact op sequence (no contraction):
#define LIF_STEP(Y, G, B, V, S)                                                \
    {                                                                          \
        const float yy = __fadd_rn(                                            \
            __fmul_rn(__fmul_rn(__fsub_rn((Y), mu), rs), (G)), (B));           \
        (V) = __fadd_rn((V), __fmul_rn(__fsub_rn(yy, (V)), 0.5f));             \
        (S) = ((V) >= 1.0f) ? 1.f : 0.f;                                       \
        (V) = __fmul_rn((V), __fsub_rn(1.0f, (S)));                            \
    }

// ---------------------------------------------------------------------------
// LIF layer 1: one block per (b,l); 384 threads x float4 cover H=1536.
// ALL Tc timestep loads issued up front (independent of the v recurrence;
// MLP=4, overlapping the stats computation). Emits PACKED BITMASKS.
// ---------------------------------------------------------------------------
__global__ __launch_bounds__(384) void lif1_kernel(
    const float* __restrict__ g1, const float* __restrict__ be1) {
    __shared__ float2 st[Tc];
    const int bl = blockIdx.x;
    const int bI = bl / Lc, l = bl % Lc;
    const int rbase = bI * Lc + l;
    const int c = threadIdx.x * 4;

    // batched loads of all 4 timestep rows (before the stats sync)
    float4 y[Tc];
#pragma unroll
    for (int t = 0; t < Tc; t++)
        y[t] = *(const float4*)(g_h1 + (size_t)(t * (Bc * Lc) + rbase) * Hc + c);

    if (threadIdx.x < Tc) {
        const int r = threadIdx.x * (Bc * Lc) + rbase;
        st[threadIdx.x] = stats_from_p1(g_p1 + (size_t)r * NB1);
    }
    const int wp = threadIdx.x >> 5;
    const int lane = threadIdx.x & 31;
    const unsigned FULL = 0xffffffffu;
    const float4 gg = *(const float4*)(g1 + c);
    const float4 bb = *(const float4*)(be1 + c);
    float4 v = {0.f, 0.f, 0.f, 0.f};
    __syncthreads();
#pragma unroll
    for (int t = 0; t < Tc; t++) {
        const int r = t * (Bc * Lc) + rbase;
        const float mu = st[t].x, rs = st[t].y;
        float4 sp;
        LIF_STEP(y[t].x, gg.x, bb.x, v.x, sp.x)
        LIF_STEP(y[t].y, gg.y, bb.y, v.y, sp.y)
        LIF_STEP(y[t].z, gg.z, bb.z, v.z, sp.z)
        LIF_STEP(y[t].w, gg.w, bb.w, v.w, sp.w)
        const unsigned mm = (sp.x != 0.f ? 1u : 0u) | (sp.y != 0.f ? 2u : 0u) |
                            (sp.z != 0.f ? 4u : 0u) | (sp.w != 0.f ? 8u : 0u);
        unsigned long long m = (unsigned long long)mm << ((lane & 15) * 4);
        m |= __shfl_xor_sync(FULL, m, 1);
        m |= __shfl_xor_sync(FULL, m, 2);
        m |= __shfl_xor_sync(FULL, m, 4);
        m |= __shfl_xor_sync(FULL, m, 8);
        if ((lane & 15) == 0)
            g_m1[(size_t)r * MWORDS + 2 * wp + (lane >> 4)] = m;
    }
}

// ---------------------------------------------------------------------------
// Sparse-exact GEMM2: h2[m,d] = b2[d] + sum_{k: spike(m,k)} W2T[k,d], adds in
// ascending k. Bit-identical to the dense fp32 fma chain (fma(0,..)=acc,
// fma(1,w,acc)=fadd_rn(acc,w); acc never -0).
// 512 threads (16 warps x 2 rows), CHUNK=32, double-buffered, 2 CTAs/SM.
// Mask words PREFETCHED one word (=2 chunks) ahead so the per-chunk L2
// latency (~240cyc) hides under the previous word's walk.
// ---------------------------------------------------------------------------
#define ADD_ROW(A0, A1, A2)                                                    \
    A0.x = __fadd_rn(A0.x, w0.x); A0.y = __fadd_rn(A0.y, w0.y);                \
    A0.z = __fadd_rn(A0.z, w0.z); A0.w = __fadd_rn(A0.w, w0.w);                \
    A1.x = __fadd_rn(A1.x, w1.x); A1.y = __fadd_rn(A1.y, w1.y);                \
    A1.z = __fadd_rn(A1.z, w1.z); A1.w = __fadd_rn(A1.w, w1.w);                \
    A2.x = __fadd_rn(A2.x, w2v.x); A2.y = __fadd_rn(A2.y, w2v.y);              \
    A2.z = __fadd_rn(A2.z, w2v.z); A2.w = __fadd_rn(A2.w, w2v.w);

__global__ __launch_bounds__(SP_THREADS, 2) void spmm2_kernel(
    const float* __restrict__ b2) {
    extern __shared__ float w2s[];   // 2 * CHUNK_FLOATS (96KB)
    const int tid = threadIdx.x;
    const int warp = tid >> 5, lane = tid & 31;
    const int rbase = blockIdx.x * SP_ROWS + warp * 2;
    const int lane12 = lane * 12;
    const unsigned FULL = 0xffffffffu;

    // prologue: async copy chunk 0 (3072 float4s, 512 threads x 6)
    {
        const float4* src = (const float4*)g_w2t;
        float4* dst = (float4*)w2s;
#pragma unroll
        for (int i = 0; i < 6; i++)
            __pipeline_memcpy_async(dst + tid + i * 512, src + tid + i * 512, 16);
        __pipeline_commit();
    }

    const unsigned long long* mrow0 = g_m1 + (size_t)rbase * MWORDS;
    const unsigned long long* mrow1 = g_m1 + (size_t)(rbase + 1) * MWORDS;

    float4 a00 = {0,0,0,0}, a01 = {0,0,0,0}, a02 = {0,0,0,0};
    float4 a10 = {0,0,0,0}, a11 = {0,0,0,0}, a12 = {0,0,0,0};

    unsigned long long cur0 = mrow0[0];
    unsigned long long cur1 = mrow1[0];

    for (int w = 0; w < MWORDS; w++) {
        // prefetch next word's masks (L2 latency hidden under this word's walk)
        unsigned long long nx0 = 0ULL, nx1 = 0ULL;
        if (w + 1 < MWORDS) {
            nx0 = mrow0[w + 1];
            nx1 = mrow1[w + 1];
        }
#pragma unroll
        for (int half = 0; half < 2; half++) {
            const int c = 2 * w + half;
            unsigned u0 = (unsigned)(cur0 >> (half * 32));
            unsigned u1 = (unsigned)(cur1 >> (half * 32));
            __syncthreads();   // all warps done reading buf[(c+1)&1] (chunk c-1)
            if (c + 1 < NCHUNK) {
                const float4* src = (const float4*)(g_w2t + (size_t)(c + 1) * CHUNK_FLOATS);
                float4* dst = (float4*)(w2s + ((c + 1) & 1) * CHUNK_FLOATS);
#pragma unroll
                for (int i = 0; i < 6; i++)
                    __pipeline_memcpy_async(dst + tid + i * 512, src + tid + i * 512, 16);
                __pipeline_commit();
                __pipeline_wait_prior(1);
            } else {
                __pipeline_wait_prior(0);
            }
            __syncthreads();   // chunk c resident in buf[c&1]

            const float* wbase = w2s + (c & 1) * CHUNK_FLOATS + lane12;
            while (u0 | u1) {
                if (u0) {
                    const int j = __ffs(u0) - 1;
                    u0 &= u0 - 1;
                    const float4* wr = (const float4*)(wbase + j * Dc);
                    const float4 w0 = wr[0], w1 = wr[1], w2v = wr[2];
                    ADD_ROW(a00, a01, a02)
                }
                if (u1) {
                    const int j = __ffs(u1) - 1;
                    u1 &= u1 - 1;
                    const float4* wr = (const float4*)(wbase + j * Dc);
                    const float4 w0 = wr[0], w1 = wr[1], w2v = wr[2];
                    ADD_ROW(a10, a11, a12)
                }
            }
        }
        cur0 = nx0;
        cur1 = nx1;
    }

    // epilogue: bias, store h2, per-row stats
    const float4 bb0 = *(const float4*)(b2 + lane12);
    const float4 bb1 = *(const float4*)(b2 + lane12 + 4);
    const float4 bb2 = *(const float4*)(b2 + lane12 + 8);
#pragma unroll
    for (int rr = 0; rr < 2; rr++) {
        const float4 A0 = rr ? a10 : a00;
        const float4 A1 = rr ? a11 : a01;
        const float4 A2 = rr ? a12 : a02;
        float4 o0, o1, o2;
        o0.x = __fadd_rn(A0.x, bb0.x); o0.y = __fadd_rn(A0.y, bb0.y);
        o0.z = __fadd_rn(A0.z, bb0.z); o0.w = __fadd_rn(A0.w, bb0.w);
        o1.x = __fadd_rn(A1.x, bb1.x); o1.y = __fadd_rn(A1.y, bb1.y);
        o1.z = __fadd_rn(A1.z, bb1.z); o1.w = __fadd_rn(A1.w, bb1.w);
        o2.x = __fadd_rn(A2.x, bb2.x); o2.y = __fadd_rn(A2.y, bb2.y);
        o2.z = __fadd_rn(A2.z, bb2.z); o2.w = __fadd_rn(A2.w, bb2.w);
        const int row = rbase + rr;
        float* q = g_h2 + (size_t)row * Dc + lane12;
        *(float4*)q = o0; *(float4*)(q + 4) = o1; *(float4*)(q + 8) = o2;

        // f32 lane partials, f64 butterfly (same accuracy class as g_p1 path)
        const float sf = P4(o0.x, o0.y, o0.z, o0.w) +
                         P4(o1.x, o1.y, o1.z, o1.w) +
                         P4(o2.x, o2.y, o2.z, o2.w);
        const float qf = P4(o0.x * o0.x, o0.y * o0.y, o0.z * o0.z, o0.w * o0.w) +
                         P4(o1.x * o1.x, o1.y * o1.y, o1.z * o1.z, o1.w * o1.w) +
                         P4(o2.x * o2.x, o2.y * o2.y, o2.z * o2.z, o2.w * o2.w);
        double sd = (double)sf, qd = (double)qf;
#pragma unroll
        for (int o = 16; o; o >>= 1) {
            sd += __shfl_xor_sync(FULL, sd, o);
            qd += __shfl_xor_sync(FULL, qd, o);
        }
        if (lane == 0) {
            const double mu_d = sd / (double)Dc;
            const float var = (float)(qd / (double)Dc - mu_d * mu_d);
            g_st2[row] = make_float2(
                (float)mu_d,
                __fdiv_rn(1.0f, __fsqrt_rn(__fadd_rn(var, 1e-5f))));
        }
    }
}

// ---------------------------------------------------------------------------
// LIF layer 2 -> final output [B,T,L,D]. 384 threads = 4 (b,l) rows x 96
// lanes x float4 (D=384). Stats read from g_st2.
// ---------------------------------------------------------------------------
__global__ __launch_bounds__(384) void lif2_kernel(
    const float* __restrict__ g2, const float* __restrict__ be2,
    float* __restrict__ out) {
    __shared__ float2 st[4][Tc];
    if (threadIdx.x < 16) {
        const int sub_ = threadIdx.x >> 2;
        const int t_ = threadIdx.x & 3;
        const int bl_ = blockIdx.x * 4 + sub_;
        const int r = t_ * (Bc * Lc) + (bl_ / Lc) * Lc + (bl_ % Lc);
        st[sub_][t_] = g_st2[r];
    }
    const int sub = threadIdx.x / 96;        // 0..3
    const int bl = blockIdx.x * 4 + sub;
    const int bI = bl / Lc, l = bl % Lc;
    const int c = (threadIdx.x % 96) * 4;
    const float4 gg = *(const float4*)(g2 + c);
    const float4 bb = *(const float4*)(be2 + c);
    float4 v = {0.f, 0.f, 0.f, 0.f};
    const int rbase = bI * Lc + l;

    // batched loads of all 4 timestep rows
    float4 y[Tc];
#pragma unroll
    for (int t = 0; t < Tc; t++)
        y[t] = *(const float4*)(g_h2 + (size_t)(t * (Bc * Lc) + rbase) * Dc + c);

    __syncthreads();
#pragma unroll
    for (int t = 0; t < Tc; t++) {
        const float mu = st[sub][t].x, rs = st[sub][t].y;
        float4 sp;
        LIF_STEP(y[t].x, gg.x, bb.x, v.x, sp.x)
        LIF_STEP(y[t].y, gg.y, bb.y, v.y, sp.y)
        LIF_STEP(y[t].z, gg.z, bb.z, v.z, sp.z)
        LIF_STEP(y[t].w, gg.w, bb.w, v.w, sp.w)
        const size_t oo = (size_t)((bI * Tc + t) * Lc + l) * Dc + c;
        *(float4*)(out + oo) = sp;
    }
}

// ---------------------------------------------------------------------------
extern "C" void kernel_launch(void* const* d_in, const int* in_sizes, int n_in,
                              void* d_out, int out_size) {
    const float* x   = (const float*)d_in[0];
    const float* W1  = (const float*)d_in[1];
    const float* b1  = (const float*)d_in[2];
    const float* g1  = (const float*)d_in[3];
    const float* be1 = (const float*)d_in[4];
    const float* W2  = (const float*)d_in[5];
    const float* b2  = (const float*)d_in[6];
    const float* g2  = (const float*)d_in[7];
    const float* be2 = (const float*)d_in[8];
    float* out = (float*)d_out;

    cudaFuncSetAttribute(spmm2_kernel,
                         cudaFuncAttributeMaxDynamicSharedMemorySize,
                         2 * CHUNK_FLOATS * (int)sizeof(float));

    w2t_kernel<<<dim3(Hc / 32, Dc / 32), dim3(32, 8)>>>(W2);
    gemm1_kernel<<<dim3(Hc / 128, Mrows / 128), 256>>>(x, W1, b1);
    lif1_kernel<<<Bc * Lc, 384>>>(g1, be1);
    spmm2_kernel<<<Mrows / SP_ROWS, SP_THREADS,
                   2 * CHUNK_FLOATS * sizeof(float)>>>(b2);
    lif2_kernel<<<(Bc * Lc) / 4, 384>>>(g2, be2, out);
}